// round 15
// baseline (speedup 1.0000x reference)
#include <cuda_runtime.h>
#include <cuda_fp16.h>
#include <math.h>
#include <stdint.h>

#define Bc   2
#define Nc   256
#define INc  256
#define Hc   8
#define Dc   64
#define HDc  512
#define ALPHA 0.2f
#define LN_EPS 1e-5f

__device__ float g_xn[Bc * Nc * INc];
__device__ float g_hs[Bc * Nc * HDc];
__device__ float g_ht[Bc * Nc * HDc];
__device__ float g_scores[(size_t)Bc * Nc * Nc * Hc];
__device__ float g_den[Bc * Nc * Hc];
__device__ float g_nn[Bc * Nc * Dc];
__device__ float g_z1[Bc * Nc * INc];
__device__ float g_z2[Bc * Nc * INc];
// k2 weights: k32-blocked n-major [k>>5][n][k&31]
__device__ __half g_We16b[INc * HDc];
// k4 weights: k16-blocked n-major [k>>4][n][k&15]
__device__ __half g_W3H[INc * INc];

__device__ __forceinline__ void mma16(float* c, const uint32_t* a,
                                      uint32_t b0, uint32_t b1) {
    asm volatile(
        "mma.sync.aligned.m16n8k16.row.col.f32.f16.f16.f32 "
        "{%0,%1,%2,%3},{%4,%5,%6,%7},{%8,%9},{%0,%1,%2,%3};\n"
        : "+f"(c[0]), "+f"(c[1]), "+f"(c[2]), "+f"(c[3])
        : "r"(a[0]), "r"(a[1]), "r"(a[2]), "r"(a[3]), "r"(b0), "r"(b1));
}
__device__ __forceinline__ void ldsm4(uint32_t* r, uint32_t addr) {
    asm volatile("ldmatrix.sync.aligned.m8n8.x4.shared.b16 {%0,%1,%2,%3}, [%4];\n"
        : "=r"(r[0]), "=r"(r[1]), "=r"(r[2]), "=r"(r[3]) : "r"(addr));
}
__device__ __forceinline__ void cp16(uint32_t dst, const void* src) {
    asm volatile("cp.async.cg.shared.global [%0], [%1], 16;\n" :: "r"(dst), "l"(src));
}
#define CP_COMMIT asm volatile("cp.async.commit_group;\n" ::)
#define CP_WAIT0  asm volatile("cp.async.wait_group 0;\n" ::)

// ============================================================
// K0a: We -> fp16 k32-blocked layout
// ============================================================
__global__ void k0a_prep(const float* __restrict__ We) {
    int i = blockIdx.x * 512 + threadIdx.x;
    if (i < INc * HDc) {
        int k = i >> 9, n = i & 511;
        g_We16b[(k >> 5) * (512 * 32) + n * 32 + (k & 31)] = __float2half(We[i]);
    }
}

// ============================================================
// K0b: W3 -> fp16 k16-blocked; zero g_den, g_nn
// ============================================================
__global__ void k0b_prep(const float* __restrict__ Wedge) {
    int i = blockIdx.x * 512 + threadIdx.x;
    if (i < INc * INc) {
        int k = i >> 8, n = i & 255;
        g_W3H[(k >> 4) * 4096 + n * 16 + (k & 15)] =
            __float2half(Wedge[(size_t)(512 + k) * 256 + n]);
    }
    if (i < Bc * Nc * Hc) g_den[i] = 0.f;
    if (i < Bc * Nc * Dc) g_nn[i] = 0.f;
}

// ============================================================
// K1: xn = emb_node*mask; h_{s,t} = xn @ W{s,t}. 16 rows/block.
// ============================================================
__global__ void k1_nodes(const float* __restrict__ emb_node,
                         const float* __restrict__ mask,
                         const float* __restrict__ Ws,
                         const float* __restrict__ Wt) {
    __shared__ float xs[16][INc];
    int t = threadIdx.x;
    int n0 = blockIdx.x * 16;
    const float* W  = blockIdx.y ? Wt : Ws;
    float* out      = blockIdx.y ? g_ht : g_hs;
    #pragma unroll
    for (int u = 0; u < 8; u++) {
        int lin = u * 512 + t;
        int r = lin >> 8, c = lin & 255;
        float v = emb_node[(size_t)(n0 + r) * INc + c] * mask[n0 + r];
        xs[r][c] = v;
        if (blockIdx.y == 0) g_xn[(size_t)(n0 + r) * INc + c] = v;
    }
    __syncthreads();
    float a[16];
    #pragma unroll
    for (int r = 0; r < 16; r++) a[r] = 0.f;
    #pragma unroll 4
    for (int k = 0; k < INc; k++) {
        float wv = W[(size_t)k * HDc + t];
        #pragma unroll
        for (int r = 0; r < 16; r++) a[r] = fmaf(xs[r][k], wv, a[r]);
    }
    #pragma unroll
    for (int r = 0; r < 16; r++)
        out[(size_t)(n0 + r) * HDc + t] = a[r];
}

// ============================================================
// K2: fp16 scores, PERSISTENT, 4-stage B pipeline, wait+sync
// every 2 chunks. grid = #SMs, 256 threads, occ 1. (R13/R14 ver)
// SMEM u32: A[64][132]=8448 | B 4x[512][20]=40960 | hs 512 | at 512
// ============================================================
#define K2_TILES (Bc * Nc * 4)
#define K2_SMEM_B ((8448 + 40960 + 512 + 512) * 4)
__global__ void __launch_bounds__(256, 1)
k2_scores(const float* __restrict__ emb_edge,
          const float* __restrict__ adj,
          const float* __restrict__ mask,
          const float* __restrict__ attn) {
    extern __shared__ uint32_t su[];
    uint32_t* sA  = su;
    uint32_t* sB  = su + 8448;
    float*    sHS = (float*)(su + 49408);
    float*    sAT = (float*)(su + 49920);

    int t = threadIdx.x, wc = t >> 5, lane = t & 31;
    int g = lane >> 2, tig = lane & 3;
    int lm = lane & 7, lq = lane >> 3;
    int aRow = lm + (lq & 1) * 8;
    int aCol = (lq >> 1) * 8;
    int bRow = wc * 64 + (lq >> 1) * 8 + lm;
    int bCol = (lq & 1) * 8;

    uint32_t sAsh = (uint32_t)__cvta_generic_to_shared(sA);
    uint32_t sBsh = (uint32_t)__cvta_generic_to_shared(sB);

    #pragma unroll
    for (int u = 0; u < 2; u++) sAT[u * 256 + t] = attn[u * 256 + t];

    for (int tile = blockIdx.x; tile < K2_TILES; tile += gridDim.x) {
        int jt = tile & 3, i = (tile >> 2) & 255, b = tile >> 10;
        int j0 = jt * 64, bi = b * Nc + i;
        float mi = mask[bi];

        #pragma unroll
        for (int c = 0; c < 2; c++) {
            #pragma unroll
            for (int q = 0; q < 8; q++) {
                int t8 = q * 256 + t;
                int n = t8 >> 2, kq = t8 & 3;
                cp16(sBsh + (c * 10240 + n * 20 + kq * 4) * 4,
                     g_We16b + (size_t)c * 16384 + (size_t)t8 * 8);
            }
            CP_COMMIT;
        }

        #pragma unroll
        for (int u = 0; u < 16; u++) {
            int lin = u * 256 + t;
            int r = lin >> 6, c4 = lin & 63;
            float4 v = *(const float4*)(emb_edge +
                (((size_t)bi * Nc) + j0 + r) * INc + c4 * 4);
            float mm = mi * mask[b * Nc + j0 + r];
            __half2 h01 = __floats2half2_rn(v.x * mm, v.y * mm);
            __half2 h23 = __floats2half2_rn(v.z * mm, v.w * mm);
            uint32_t* dst = sA + r * 132 + c4 * 2;
            dst[0] = *reinterpret_cast<uint32_t*>(&h01);
            dst[1] = *reinterpret_cast<uint32_t*>(&h23);
        }
        #pragma unroll
        for (int u = 0; u < 2; u++)
            sHS[u * 256 + t] = g_hs[(size_t)bi * HDc + u * 256 + t];

        float acc[4][8][4];
        #pragma unroll
        for (int m = 0; m < 4; m++)
            #pragma unroll
            for (int n = 0; n < 8; n++)
                #pragma unroll
                for (int e = 0; e < 4; e++) acc[m][n][e] = 0.f;

        for (int c = 0; c < 8; c++) {
            if ((c & 1) == 0) {
                CP_WAIT0;
                __syncthreads();
            }
            if (c + 2 < 8) {
                int cc = c + 2;
                #pragma unroll
                for (int q = 0; q < 8; q++) {
                    int t8 = q * 256 + t;
                    int n = t8 >> 2, kq = t8 & 3;
                    cp16(sBsh + ((cc & 3) * 10240 + n * 20 + kq * 4) * 4,
                         g_We16b + (size_t)cc * 16384 + (size_t)t8 * 8);
                }
                CP_COMMIT;
            }
            uint32_t stOff = sBsh + (c & 3) * 40960;
            uint32_t af[2][4][4];
            uint32_t bf[2][4][4];
            #pragma unroll
            for (int kk = 0; kk < 2; kk++) {
                int kh = c * 32 + kk * 16;
                #pragma unroll
                for (int mf = 0; mf < 4; mf++)
                    ldsm4(af[kk][mf], sAsh + ((mf * 16 + aRow) * 264 + kh + aCol) * 2);
                #pragma unroll
                for (int p = 0; p < 4; p++)
                    ldsm4(bf[kk][p], stOff + ((bRow + p * 16) * 40 + kk * 16 + bCol) * 2);
            }
            #pragma unroll
            for (int kk = 0; kk < 2; kk++)
                #pragma unroll
                for (int p = 0; p < 4; p++)
                    #pragma unroll
                    for (int mf = 0; mf < 4; mf++) {
                        mma16(acc[mf][2 * p],     af[kk][mf], bf[kk][p][0], bf[kk][p][1]);
                        mma16(acc[mf][2 * p + 1], af[kk][mf], bf[kk][p][2], bf[kk][p][3]);
                    }
        }

        float wsum = 0.f;
        #pragma unroll
        for (int mf = 0; mf < 4; mf++) {
            #pragma unroll
            for (int rh = 0; rh < 2; rh++) {
                int j = j0 + mf * 16 + g + 8 * rh;
                const float* htrow = g_ht + (size_t)(b * Nc + j) * HDc + wc * 64;
                float sum = 0.f;
                #pragma unroll
                for (int n = 0; n < 8; n++) {
                    int c0 = n * 8 + 2 * tig;
                    float2 hte = *(const float2*)(htrow + c0);
                    float2 hs2 = *(const float2*)(sHS + wc * 64 + c0);
                    float2 at2 = *(const float2*)(sAT + wc * 64 + c0);
                    float v0 = acc[mf][n][2 * rh]     + hs2.x + hte.x;
                    float v1 = acc[mf][n][2 * rh + 1] + hs2.y + hte.y;
                    v0 = v0 > 0.f ? v0 : ALPHA * v0;
                    v1 = v1 > 0.f ? v1 : ALPHA * v1;
                    sum = fmaf(at2.x, v0, sum);
                    sum = fmaf(at2.y, v1, sum);
                }
                sum += __shfl_xor_sync(0xffffffffu, sum, 1);
                sum += __shfl_xor_sync(0xffffffffu, sum, 2);
                if (tig == 0) {
                    size_t e = (size_t)bi * Nc + j;
                    float sv = expf(sum) * adj[e] * (mi * mask[b * Nc + j]);
                    g_scores[e * 8 + wc] = sv;
                    wsum += sv;
                }
            }
        }
        wsum += __shfl_xor_sync(0xffffffffu, wsum, 4);
        wsum += __shfl_xor_sync(0xffffffffu, wsum, 8);
        wsum += __shfl_xor_sync(0xffffffffu, wsum, 16);
        if (lane == 0) atomicAdd(&g_den[bi * 8 + wc], wsum);

        __syncthreads();
    }
}

// ============================================================
// K3b: new_node einsum, j-split. grid (32, 2, 2). 512 thr.
// ============================================================
#define K3B_SMEM_B ((8192 + 64 + 4096) * 4)
__global__ void __launch_bounds__(512, 1) k3b_newnode() {
    extern __shared__ float smf[];
    float* s_sh = smf;
    float* inv  = smf + 8192;
    float* redn = smf + 8256;
    int t = threadIdx.x;
    int b = blockIdx.y, i0 = blockIdx.x * 8, bi0 = b * Nc + i0;
    int jz = blockIdx.z;
    if (t < 64) {
        int r = t >> 3, h = t & 7;
        inv[t] = 1.f / (g_den[(bi0 + r) * 8 + h] + 1e-6f);
    }
    __syncthreads();
    #pragma unroll
    for (int u = 0; u < 16; u++) {
        int lin = u * 512 + t;
        int r = lin >> 10, jh = lin & 1023;
        s_sh[r * 1024 + jh] =
            g_scores[(size_t)(bi0 + r) * 2048 + jz * 1024 + jh] *
            inv[r * 8 + (jh & 7)];
    }
    __syncthreads();
    int js = t >> 6, d = t & 63;
    float a[8];
    #pragma unroll
    for (int r = 0; r < 8; r++) a[r] = 0.f;
    const float* htb = g_ht + (size_t)b * Nc * HDc;
    for (int jj = 0; jj < 16; jj++) {
        int jl = js * 16 + jj;
        const float* hp = htb + (size_t)(jz * 128 + jl) * HDc + d;
        #pragma unroll
        for (int h = 0; h < 8; h++) {
            float htv = hp[h * 64];
            #pragma unroll
            for (int r = 0; r < 8; r++)
                a[r] = fmaf(s_sh[r * 1024 + jl * 8 + h], htv, a[r]);
        }
    }
    #pragma unroll
    for (int r = 0; r < 8; r++) redn[js * 512 + r * 64 + d] = a[r];
    __syncthreads();
    {
        int r = t >> 6, dd = t & 63;
        float s = 0.f;
        #pragma unroll
        for (int q = 0; q < 8; q++) s += redn[q * 512 + r * 64 + dd];
        atomicAdd(&g_nn[(size_t)(bi0 + r) * Dc + dd], s);
    }
}

// ============================================================
// K3c: np = nn@Wn + bn; node LN; z1/z2 projections.
// ============================================================
__global__ void __launch_bounds__(512, 1)
k3c_node(const float* __restrict__ Wn,
         const float* __restrict__ bn,
         const float* __restrict__ Wedge,
         const float* __restrict__ gamma_x,
         const float* __restrict__ beta_x,
         float* __restrict__ out_node) {
    __shared__ float nn_sh[8][Dc];
    __shared__ float np_sh[8][INc];
    __shared__ float vsh[8][INc];
    __shared__ float mean_sh[8], rstd_sh[8];
    int t = threadIdx.x, w = t >> 5, lane = t & 31;
    int bi0 = blockIdx.x * 8;
    {
        int r = t >> 6, d = t & 63;
        nn_sh[r][d] = g_nn[(size_t)(bi0 + r) * Dc + d];
    }
    __syncthreads();
    int c = t & 255, rp = t >> 8;
    float np[4];
    #pragma unroll
    for (int rr = 0; rr < 4; rr++) np[rr] = bn[c];
    #pragma unroll 4
    for (int d = 0; d < Dc; d++) {
        float wv = Wn[(size_t)d * INc + c];
        #pragma unroll
        for (int rr = 0; rr < 4; rr++)
            np[rr] = fmaf(nn_sh[rp * 4 + rr][d], wv, np[rr]);
    }
    #pragma unroll
    for (int rr = 0; rr < 4; rr++) {
        int r = rp * 4 + rr;
        np_sh[r][c] = np[rr];
        vsh[r][c] = g_xn[(size_t)(bi0 + r) * INc + c] + np[rr];
    }
    __syncthreads();
    if (w < 8) {
        float s = 0.f, sq = 0.f;
        #pragma unroll
        for (int u = 0; u < 8; u++) {
            float v = vsh[w][lane + u * 32];
            s += v; sq = fmaf(v, v, sq);
        }
        #pragma unroll
        for (int off = 16; off > 0; off >>= 1) {
            s  += __shfl_xor_sync(0xffffffffu, s, off);
            sq += __shfl_xor_sync(0xffffffffu, sq, off);
        }
        if (lane == 0) {
            float mean = s * (1.f / 256.f);
            mean_sh[w] = mean;
            rstd_sh[w] = rsqrtf(sq * (1.f / 256.f) - mean * mean + LN_EPS);
        }
    }
    __syncthreads();
    #pragma unroll
    for (int rr = 0; rr < 4; rr++) {
        int r = rp * 4 + rr;
        out_node[(size_t)(bi0 + r) * INc + c] =
            (vsh[r][c] - mean_sh[r]) * rstd_sh[r] * gamma_x[c] + beta_x[c];
    }
    float z1a[4] = {0.f, 0.f, 0.f, 0.f}, z2a[4] = {0.f, 0.f, 0.f, 0.f};
    #pragma unroll 2
    for (int k = 0; k < INc; k++) {
        float w1 = Wedge[(size_t)k * INc + c];
        float w2 = Wedge[(size_t)(k + 256) * INc + c];
        #pragma unroll
        for (int rr = 0; rr < 4; rr++) {
            float npv = np_sh[rp * 4 + rr][k];
            z1a[rr] = fmaf(npv, w1, z1a[rr]);
            z2a[rr] = fmaf(npv, w2, z2a[rr]);
        }
    }
    #pragma unroll
    for (int rr = 0; rr < 4; rr++) {
        int r = rp * 4 + rr;
        g_z1[(size_t)(bi0 + r) * INc + c] = z1a[rr];
        g_z2[(size_t)(bi0 + r) * INc + c] = z2a[rr];
    }
}

// ============================================================
// K4: fp16 z3 GEMM + residual + LN. 256 thr, 8 warps, OCC 2.
// Block tile 64x256, K=256 (16 k16 chunks), 6-stage B pipeline,
// wait+sync every 2 chunks (8 barrier pairs). Warp tile 64x32.
// smem bytes: A16 0..33792 | B 6x12288 @33792..107520 |
//  Z1@107520 BE@108544 GA@109568 BT@110592 -> 111616
//  LN buffers overlay dead B stages 0-1 (post-mainloop):
//  Red@33792 RedQ@35840 Mean@37888 Rstd@38144
// ============================================================
#define K4_SMEM 111616
__global__ void __launch_bounds__(256, 2)
k4_fused(const float* __restrict__ emb_edge,
         const float* __restrict__ mask,
         const float* __restrict__ bedge,
         const float* __restrict__ gamma_e,
         const float* __restrict__ beta_e,
         float* __restrict__ out_edge) {
    extern __shared__ char sm[];
    uint32_t base = (uint32_t)__cvta_generic_to_shared(sm);
    uint32_t* sA   = (uint32_t*)sm;
    float*    sZ1  = (float*)(sm + 107520);
    float*    sBE  = (float*)(sm + 108544);
    float*    sGA  = (float*)(sm + 109568);
    float*    sBT  = (float*)(sm + 110592);
    float*    sRed = (float*)(sm + 33792);   // overlays B stage 0 (dead in epi)
    float*    sRedQ= (float*)(sm + 35840);
    float*    sMean= (float*)(sm + 37888);
    float*    sRstd= (float*)(sm + 38144);

    int t = threadIdx.x, wc = t >> 5, lane = t & 31;
    int g = lane >> 2, tig = lane & 3;
    int lm = lane & 7, lq = lane >> 3;
    int bid = blockIdx.x;
    int jt = bid & 3, i = (bid >> 2) & 255, b = bid >> 10;
    int j0 = jt * 64, bi = b * Nc + i, bN = b * Nc;
    float mi = mask[bi];

    // prefetch B chunks 0,1 into stages 0,1
    #pragma unroll
    for (int s = 0; s < 2; s++) {
        #pragma unroll
        for (int q = 0; q < 2; q++) {
            int idx = q * 256 + t;
            int n = idx >> 1, h = idx & 1;
            cp16(base + 33792 + s * 12288 + n * 48 + h * 16,
                 g_W3H + (size_t)s * 4096 + n * 16 + h * 8);
        }
        CP_COMMIT;
    }
    // stage A (masked xe -> fp16)
    #pragma unroll
    for (int u = 0; u < 16; u++) {
        int lin = u * 256 + t;
        int r = lin >> 6, c4 = lin & 63;
        float4 v = *(const float4*)(emb_edge +
            (((size_t)bi * Nc) + j0 + r) * INc + c4 * 4);
        float mm = mi * mask[bN + j0 + r];
        __half2 h01 = __floats2half2_rn(v.x * mm, v.y * mm);
        __half2 h23 = __floats2half2_rn(v.z * mm, v.w * mm);
        uint32_t* dst = sA + r * 132 + c4 * 2;
        dst[0] = *reinterpret_cast<uint32_t*>(&h01);
        dst[1] = *reinterpret_cast<uint32_t*>(&h23);
    }
    sZ1[t] = g_z1[(size_t)bi * INc + t];
    sBE[t] = bedge[t]; sGA[t] = gamma_e[t]; sBT[t] = beta_e[t];

    int aRow = lm + (lq & 1) * 8;
    int aColH = (lq >> 1) * 8;
    int bRowBase = wc * 32 + (lq >> 1) * 8 + lm;
    int bColByte = (lq & 1) * 16;

    float acc[4][4][4];
    #pragma unroll
    for (int m = 0; m < 4; m++)
        #pragma unroll
        for (int n = 0; n < 4; n++)
            #pragma unroll
            for (int e = 0; e < 4; e++) acc[m][n][e] = 0.f;

    for (int c = 0; c < 16; c++) {
        if ((c & 1) == 0) {
            CP_WAIT0;
            __syncthreads();
        }
        if (c + 2 < 16) {
            int cc = c + 2;
            int st = cc % 6;
            #pragma unroll
            for (int q = 0; q < 2; q++) {
                int idx = q * 256 + t;
                int n = idx >> 1, h = idx & 1;
                cp16(base + 33792 + st * 12288 + n * 48 + h * 16,
                     g_W3H + (size_t)cc * 4096 + n * 16 + h * 8);
            }
            CP_COMMIT;
        }
        uint32_t bO = base + 33792 + (c % 6) * 12288;
        uint32_t af[4][4];
        uint32_t bf[2][4];
        #pragma unroll
        for (int mf = 0; mf < 4; mf++)
            ldsm4(af[mf], base + ((mf * 16 + aRow) * 264 + c * 16 + aColH) * 2);
        #pragma unroll
        for (int p = 0; p < 2; p++)
            ldsm4(bf[p], bO + (uint32_t)(bRowBase + p * 16) * 48 + bColByte);
        #pragma unroll
        for (int p = 0; p < 2; p++)
            #pragma unroll
            for (int mf = 0; mf < 4; mf++) {
                mma16(acc[mf][2 * p],     af[mf], bf[p][0], bf[p][1]);
                mma16(acc[mf][2 * p + 1], af[mf], bf[p][2], bf[p][3]);
            }
    }

    // ---- epilogue: residual + LayerNorm (LN buffers overlay B st 0-1) ----
    float vv[4][2][8];
    #pragma unroll
    for (int mf = 0; mf < 4; mf++) {
        #pragma unroll
        for (int rh = 0; rh < 2; rh++) {
            int r = mf * 16 + g + 8 * rh;
            int j = j0 + r;
            float mm = mi * mask[bN + j];
            const float* xerow = emb_edge + ((size_t)bi * Nc + j) * INc;
            const float* z2row = g_z2 + (size_t)(bN + j) * INc;
            float sum = 0.f, sq = 0.f;
            #pragma unroll
            for (int n = 0; n < 4; n++) {
                int c0 = wc * 32 + n * 8 + 2 * tig;
                float2 xe2 = *(const float2*)(xerow + c0);
                float2 z22 = *(const float2*)(z2row + c0);
                float2 z12 = *(const float2*)(sZ1 + c0);
                float2 be2 = *(const float2*)(sBE + c0);
                float v0 = acc[mf][n][2 * rh]     + xe2.x * mm + z12.x + z22.x + be2.x;
                float v1 = acc[mf][n][2 * rh + 1] + xe2.y * mm + z12.y + z22.y + be2.y;
                vv[mf][rh][2 * n] = v0; vv[mf][rh][2 * n + 1] = v1;
                sum += v0 + v1;
                sq = fmaf(v0, v0, sq); sq = fmaf(v1, v1, sq);
            }
            sum += __shfl_xor_sync(0xffffffffu, sum, 1);
            sum += __shfl_xor_sync(0xffffffffu, sum, 2);
            sq  += __shfl_xor_sync(0xffffffffu, sq, 1);
            sq  += __shfl_xor_sync(0xffffffffu, sq, 2);
            if (tig == 0) { sRed[r * 8 + wc] = sum; sRedQ[r * 8 + wc] = sq; }
        }
    }
    __syncthreads();
    if (t < 64) {
        float s = 0.f, ss = 0.f;
        #pragma unroll
        for (int k = 0; k < 8; k++) { s += sRed[t * 8 + k]; ss += sRedQ[t * 8 + k]; }
        float mean = s * (1.f / 256.f);
        float var = ss * (1.f / 256.f) - mean * mean;
        sMean[t] = mean; sRstd[t] = rsqrtf(var + LN_EPS);
    }
    __syncthreads();
    #pragma unroll
    for (int mf = 0; mf < 4; mf++) {
        #pragma unroll
        for (int rh = 0; rh < 2; rh++) {
            int r = mf * 16 + g + 8 * rh;
            int j = j0 + r;
            float mean = sMean[r], rs = sRstd[r];
            float* orow = out_edge + ((size_t)bi * Nc + j) * INc;
            #pragma unroll
            for (int n = 0; n < 4; n++) {
                int c0 = wc * 32 + n * 8 + 2 * tig;
                float2 ga2 = *(const float2*)(sGA + c0);
                float2 bt2 = *(const float2*)(sBT + c0);
                float2 o;
                o.x = (vv[mf][rh][2 * n]     - mean) * rs * ga2.x + bt2.x;
                o.y = (vv[mf][rh][2 * n + 1] - mean) * rs * ga2.y + bt2.y;
                *(float2*)(orow + c0) = o;
            }
        }
    }
}

// ============================================================
extern "C" void kernel_launch(void* const* d_in, const int* in_sizes, int n_in,
                              void* d_out, int out_size) {
    const float* emb_node = (const float*)d_in[0];
    const float* emb_edge = (const float*)d_in[1];
    const float* adj      = (const float*)d_in[2];
    const float* mask     = (const float*)d_in[3];
    const float* Ws       = (const float*)d_in[4];
    const float* Wt       = (const float*)d_in[5];
    const float* We       = (const float*)d_in[6];
    const float* attn     = (const float*)d_in[7];
    const float* Wn       = (const float*)d_in[8];
    const float* bn       = (const float*)d_in[9];
    const float* Wedge    = (const float*)d_in[10];
    const float* bedge    = (const float*)d_in[11];
    const float* gamma_x  = (const float*)d_in[12];
    const float* beta_x   = (const float*)d_in[13];
    const float* gamma_e  = (const float*)d_in[14];
    const float* beta_e   = (const float*)d_in[15];

    float* out_node = (float*)d_out;
    float* out_edge = out_node + Bc * Nc * INc;

    int dev = 0, nsm = 148;
    cudaGetDevice(&dev);
    cudaDeviceGetAttribute(&nsm, cudaDevAttrMultiProcessorCount, dev);

    cudaFuncSetAttribute(k2_scores, cudaFuncAttributeMaxDynamicSharedMemorySize,
                         K2_SMEM_B);
    cudaFuncSetAttribute(k3b_newnode, cudaFuncAttributeMaxDynamicSharedMemorySize,
                         K3B_SMEM_B);
    cudaFuncSetAttribute(k4_fused, cudaFuncAttributeMaxDynamicSharedMemorySize,
                         K4_SMEM);

    k0a_prep<<<256, 512>>>(We);
    k0b_prep<<<128, 512>>>(Wedge);
    k1_nodes<<<dim3(32, 2), 512>>>(emb_node, mask, Ws, Wt);
    k2_scores<<<nsm, 256, K2_SMEM_B>>>(emb_edge, adj, mask, attn);
    k3b_newnode<<<dim3(32, 2, 2), 512, K3B_SMEM_B>>>();
    k3c_node<<<64, 512>>>(Wn, bn, Wedge, gamma_x, beta_x, out_node);
    k4_fused<<<Bc * Nc * 4, 256, K4_SMEM>>>(emb_edge, mask, bedge,
                                            gamma_e, beta_e, out_edge);
}

// round 16
// speedup vs baseline: 1.0298x; 1.0298x over previous
#include <cuda_runtime.h>
#include <cuda_fp16.h>
#include <math.h>
#include <stdint.h>

#define Bc   2
#define Nc   256
#define INc  256
#define Hc   8
#define Dc   64
#define HDc  512
#define ALPHA 0.2f
#define LN_EPS 1e-5f

__device__ float g_xn[Bc * Nc * INc];
__device__ float g_hs[Bc * Nc * HDc];
__device__ float g_ht[Bc * Nc * HDc];
__device__ float g_scores[(size_t)Bc * Nc * Nc * Hc];
__device__ float g_den[Bc * Nc * Hc];
__device__ float g_nn[Bc * Nc * Dc];
__device__ float g_z1[Bc * Nc * INc];
__device__ float g_z2[Bc * Nc * INc];
// k2 weights: k32-blocked n-major [k>>5][n][k&31]
__device__ __half g_We16b[INc * HDc];
// k4 weights: k32-blocked n-major [k>>5][n][k&31]
__device__ __half g_W3H[INc * INc];

__device__ __forceinline__ void mma16(float* c, const uint32_t* a,
                                      uint32_t b0, uint32_t b1) {
    asm volatile(
        "mma.sync.aligned.m16n8k16.row.col.f32.f16.f16.f32 "
        "{%0,%1,%2,%3},{%4,%5,%6,%7},{%8,%9},{%0,%1,%2,%3};\n"
        : "+f"(c[0]), "+f"(c[1]), "+f"(c[2]), "+f"(c[3])
        : "r"(a[0]), "r"(a[1]), "r"(a[2]), "r"(a[3]), "r"(b0), "r"(b1));
}
__device__ __forceinline__ void ldsm4(uint32_t* r, uint32_t addr) {
    asm volatile("ldmatrix.sync.aligned.m8n8.x4.shared.b16 {%0,%1,%2,%3}, [%4];\n"
        : "=r"(r[0]), "=r"(r[1]), "=r"(r[2]), "=r"(r[3]) : "r"(addr));
}
__device__ __forceinline__ void cp16(uint32_t dst, const void* src) {
    asm volatile("cp.async.cg.shared.global [%0], [%1], 16;\n" :: "r"(dst), "l"(src));
}
#define CP_COMMIT asm volatile("cp.async.commit_group;\n" ::)
#define CP_WAIT1  asm volatile("cp.async.wait_group 1;\n" ::)
#define CP_WAIT0  asm volatile("cp.async.wait_group 0;\n" ::)

// ============================================================
// K0a: We -> fp16 k32-blocked layout
// ============================================================
__global__ void k0a_prep(const float* __restrict__ We) {
    int i = blockIdx.x * 512 + threadIdx.x;
    if (i < INc * HDc) {
        int k = i >> 9, n = i & 511;
        g_We16b[(k >> 5) * (512 * 32) + n * 32 + (k & 31)] = __float2half(We[i]);
    }
}

// ============================================================
// K0b: W3 -> fp16 k32-blocked; zero g_den, g_nn
// ============================================================
__global__ void k0b_prep(const float* __restrict__ Wedge) {
    int i = blockIdx.x * 512 + threadIdx.x;
    if (i < INc * INc) {
        int k = i >> 8, n = i & 255;
        g_W3H[(k >> 5) * 8192 + n * 32 + (k & 31)] =
            __float2half(Wedge[(size_t)(512 + k) * 256 + n]);
    }
    if (i < Bc * Nc * Hc) g_den[i] = 0.f;
    if (i < Bc * Nc * Dc) g_nn[i] = 0.f;
}

// ============================================================
// K1: xn = emb_node*mask; h_{s,t} = xn @ W{s,t}. 16 rows/block.
// ============================================================
__global__ void k1_nodes(const float* __restrict__ emb_node,
                         const float* __restrict__ mask,
                         const float* __restrict__ Ws,
                         const float* __restrict__ Wt) {
    __shared__ float xs[16][INc];
    int t = threadIdx.x;
    int n0 = blockIdx.x * 16;
    const float* W  = blockIdx.y ? Wt : Ws;
    float* out      = blockIdx.y ? g_ht : g_hs;
    #pragma unroll
    for (int u = 0; u < 8; u++) {
        int lin = u * 512 + t;
        int r = lin >> 8, c = lin & 255;
        float v = emb_node[(size_t)(n0 + r) * INc + c] * mask[n0 + r];
        xs[r][c] = v;
        if (blockIdx.y == 0) g_xn[(size_t)(n0 + r) * INc + c] = v;
    }
    __syncthreads();
    float a[16];
    #pragma unroll
    for (int r = 0; r < 16; r++) a[r] = 0.f;
    #pragma unroll 4
    for (int k = 0; k < INc; k++) {
        float wv = W[(size_t)k * HDc + t];
        #pragma unroll
        for (int r = 0; r < 16; r++) a[r] = fmaf(xs[r][k], wv, a[r]);
    }
    #pragma unroll
    for (int r = 0; r < 16; r++)
        out[(size_t)(n0 + r) * HDc + t] = a[r];
}

// ============================================================
// K2: fp16 scores, PERSISTENT, 4-stage B pipeline, wait+sync
// every 2 chunks. grid = #SMs, 256 threads, occ 1. (R13/R14 ver)
// SMEM u32: A[64][132]=8448 | B 4x[512][20]=40960 | hs 512 | at 512
// ============================================================
#define K2_TILES (Bc * Nc * 4)
#define K2_SMEM_B ((8448 + 40960 + 512 + 512) * 4)
__global__ void __launch_bounds__(256, 1)
k2_scores(const float* __restrict__ emb_edge,
          const float* __restrict__ adj,
          const float* __restrict__ mask,
          const float* __restrict__ attn) {
    extern __shared__ uint32_t su[];
    uint32_t* sA  = su;
    uint32_t* sB  = su + 8448;
    float*    sHS = (float*)(su + 49408);
    float*    sAT = (float*)(su + 49920);

    int t = threadIdx.x, wc = t >> 5, lane = t & 31;
    int g = lane >> 2, tig = lane & 3;
    int lm = lane & 7, lq = lane >> 3;
    int aRow = lm + (lq & 1) * 8;
    int aCol = (lq >> 1) * 8;
    int bRow = wc * 64 + (lq >> 1) * 8 + lm;
    int bCol = (lq & 1) * 8;

    uint32_t sAsh = (uint32_t)__cvta_generic_to_shared(sA);
    uint32_t sBsh = (uint32_t)__cvta_generic_to_shared(sB);

    #pragma unroll
    for (int u = 0; u < 2; u++) sAT[u * 256 + t] = attn[u * 256 + t];

    for (int tile = blockIdx.x; tile < K2_TILES; tile += gridDim.x) {
        int jt = tile & 3, i = (tile >> 2) & 255, b = tile >> 10;
        int j0 = jt * 64, bi = b * Nc + i;
        float mi = mask[bi];

        #pragma unroll
        for (int c = 0; c < 2; c++) {
            #pragma unroll
            for (int q = 0; q < 8; q++) {
                int t8 = q * 256 + t;
                int n = t8 >> 2, kq = t8 & 3;
                cp16(sBsh + (c * 10240 + n * 20 + kq * 4) * 4,
                     g_We16b + (size_t)c * 16384 + (size_t)t8 * 8);
            }
            CP_COMMIT;
        }

        #pragma unroll
        for (int u = 0; u < 16; u++) {
            int lin = u * 256 + t;
            int r = lin >> 6, c4 = lin & 63;
            float4 v = *(const float4*)(emb_edge +
                (((size_t)bi * Nc) + j0 + r) * INc + c4 * 4);
            float mm = mi * mask[b * Nc + j0 + r];
            __half2 h01 = __floats2half2_rn(v.x * mm, v.y * mm);
            __half2 h23 = __floats2half2_rn(v.z * mm, v.w * mm);
            uint32_t* dst = sA + r * 132 + c4 * 2;
            dst[0] = *reinterpret_cast<uint32_t*>(&h01);
            dst[1] = *reinterpret_cast<uint32_t*>(&h23);
        }
        #pragma unroll
        for (int u = 0; u < 2; u++)
            sHS[u * 256 + t] = g_hs[(size_t)bi * HDc + u * 256 + t];

        float acc[4][8][4];
        #pragma unroll
        for (int m = 0; m < 4; m++)
            #pragma unroll
            for (int n = 0; n < 8; n++)
                #pragma unroll
                for (int e = 0; e < 4; e++) acc[m][n][e] = 0.f;

        for (int c = 0; c < 8; c++) {
            if ((c & 1) == 0) {
                CP_WAIT0;
                __syncthreads();
            }
            if (c + 2 < 8) {
                int cc = c + 2;
                #pragma unroll
                for (int q = 0; q < 8; q++) {
                    int t8 = q * 256 + t;
                    int n = t8 >> 2, kq = t8 & 3;
                    cp16(sBsh + ((cc & 3) * 10240 + n * 20 + kq * 4) * 4,
                         g_We16b + (size_t)cc * 16384 + (size_t)t8 * 8);
                }
                CP_COMMIT;
            }
            uint32_t stOff = sBsh + (c & 3) * 40960;
            uint32_t af[2][4][4];
            uint32_t bf[2][4][4];
            #pragma unroll
            for (int kk = 0; kk < 2; kk++) {
                int kh = c * 32 + kk * 16;
                #pragma unroll
                for (int mf = 0; mf < 4; mf++)
                    ldsm4(af[kk][mf], sAsh + ((mf * 16 + aRow) * 264 + kh + aCol) * 2);
                #pragma unroll
                for (int p = 0; p < 4; p++)
                    ldsm4(bf[kk][p], stOff + ((bRow + p * 16) * 40 + kk * 16 + bCol) * 2);
            }
            #pragma unroll
            for (int kk = 0; kk < 2; kk++)
                #pragma unroll
                for (int p = 0; p < 4; p++)
                    #pragma unroll
                    for (int mf = 0; mf < 4; mf++) {
                        mma16(acc[mf][2 * p],     af[kk][mf], bf[kk][p][0], bf[kk][p][1]);
                        mma16(acc[mf][2 * p + 1], af[kk][mf], bf[kk][p][2], bf[kk][p][3]);
                    }
        }

        float wsum = 0.f;
        #pragma unroll
        for (int mf = 0; mf < 4; mf++) {
            #pragma unroll
            for (int rh = 0; rh < 2; rh++) {
                int j = j0 + mf * 16 + g + 8 * rh;
                const float* htrow = g_ht + (size_t)(b * Nc + j) * HDc + wc * 64;
                float sum = 0.f;
                #pragma unroll
                for (int n = 0; n < 8; n++) {
                    int c0 = n * 8 + 2 * tig;
                    float2 hte = *(const float2*)(htrow + c0);
                    float2 hs2 = *(const float2*)(sHS + wc * 64 + c0);
                    float2 at2 = *(const float2*)(sAT + wc * 64 + c0);
                    float v0 = acc[mf][n][2 * rh]     + hs2.x + hte.x;
                    float v1 = acc[mf][n][2 * rh + 1] + hs2.y + hte.y;
                    v0 = v0 > 0.f ? v0 : ALPHA * v0;
                    v1 = v1 > 0.f ? v1 : ALPHA * v1;
                    sum = fmaf(at2.x, v0, sum);
                    sum = fmaf(at2.y, v1, sum);
                }
                sum += __shfl_xor_sync(0xffffffffu, sum, 1);
                sum += __shfl_xor_sync(0xffffffffu, sum, 2);
                if (tig == 0) {
                    size_t e = (size_t)bi * Nc + j;
                    float sv = expf(sum) * adj[e] * (mi * mask[b * Nc + j]);
                    g_scores[e * 8 + wc] = sv;
                    wsum += sv;
                }
            }
        }
        wsum += __shfl_xor_sync(0xffffffffu, wsum, 4);
        wsum += __shfl_xor_sync(0xffffffffu, wsum, 8);
        wsum += __shfl_xor_sync(0xffffffffu, wsum, 16);
        if (lane == 0) atomicAdd(&g_den[bi * 8 + wc], wsum);

        __syncthreads();
    }
}

// ============================================================
// K3b: new_node einsum, j-split. grid (32, 2, 2). 512 thr.
// ============================================================
#define K3B_SMEM_B ((8192 + 64 + 4096) * 4)
__global__ void __launch_bounds__(512, 1) k3b_newnode() {
    extern __shared__ float smf[];
    float* s_sh = smf;
    float* inv  = smf + 8192;
    float* redn = smf + 8256;
    int t = threadIdx.x;
    int b = blockIdx.y, i0 = blockIdx.x * 8, bi0 = b * Nc + i0;
    int jz = blockIdx.z;
    if (t < 64) {
        int r = t >> 3, h = t & 7;
        inv[t] = 1.f / (g_den[(bi0 + r) * 8 + h] + 1e-6f);
    }
    __syncthreads();
    #pragma unroll
    for (int u = 0; u < 16; u++) {
        int lin = u * 512 + t;
        int r = lin >> 10, jh = lin & 1023;
        s_sh[r * 1024 + jh] =
            g_scores[(size_t)(bi0 + r) * 2048 + jz * 1024 + jh] *
            inv[r * 8 + (jh & 7)];
    }
    __syncthreads();
    int js = t >> 6, d = t & 63;
    float a[8];
    #pragma unroll
    for (int r = 0; r < 8; r++) a[r] = 0.f;
    const float* htb = g_ht + (size_t)b * Nc * HDc;
    for (int jj = 0; jj < 16; jj++) {
        int jl = js * 16 + jj;
        const float* hp = htb + (size_t)(jz * 128 + jl) * HDc + d;
        #pragma unroll
        for (int h = 0; h < 8; h++) {
            float htv = hp[h * 64];
            #pragma unroll
            for (int r = 0; r < 8; r++)
                a[r] = fmaf(s_sh[r * 1024 + jl * 8 + h], htv, a[r]);
        }
    }
    #pragma unroll
    for (int r = 0; r < 8; r++) redn[js * 512 + r * 64 + d] = a[r];
    __syncthreads();
    {
        int r = t >> 6, dd = t & 63;
        float s = 0.f;
        #pragma unroll
        for (int q = 0; q < 8; q++) s += redn[q * 512 + r * 64 + dd];
        atomicAdd(&g_nn[(size_t)(bi0 + r) * Dc + dd], s);
    }
}

// ============================================================
// K3c: np = nn@Wn + bn; node LN; z1/z2 projections.
// ============================================================
__global__ void __launch_bounds__(512, 1)
k3c_node(const float* __restrict__ Wn,
         const float* __restrict__ bn,
         const float* __restrict__ Wedge,
         const float* __restrict__ gamma_x,
         const float* __restrict__ beta_x,
         float* __restrict__ out_node) {
    __shared__ float nn_sh[8][Dc];
    __shared__ float np_sh[8][INc];
    __shared__ float vsh[8][INc];
    __shared__ float mean_sh[8], rstd_sh[8];
    int t = threadIdx.x, w = t >> 5, lane = t & 31;
    int bi0 = blockIdx.x * 8;
    {
        int r = t >> 6, d = t & 63;
        nn_sh[r][d] = g_nn[(size_t)(bi0 + r) * Dc + d];
    }
    __syncthreads();
    int c = t & 255, rp = t >> 8;
    float np[4];
    #pragma unroll
    for (int rr = 0; rr < 4; rr++) np[rr] = bn[c];
    #pragma unroll 4
    for (int d = 0; d < Dc; d++) {
        float wv = Wn[(size_t)d * INc + c];
        #pragma unroll
        for (int rr = 0; rr < 4; rr++)
            np[rr] = fmaf(nn_sh[rp * 4 + rr][d], wv, np[rr]);
    }
    #pragma unroll
    for (int rr = 0; rr < 4; rr++) {
        int r = rp * 4 + rr;
        np_sh[r][c] = np[rr];
        vsh[r][c] = g_xn[(size_t)(bi0 + r) * INc + c] + np[rr];
    }
    __syncthreads();
    if (w < 8) {
        float s = 0.f, sq = 0.f;
        #pragma unroll
        for (int u = 0; u < 8; u++) {
            float v = vsh[w][lane + u * 32];
            s += v; sq = fmaf(v, v, sq);
        }
        #pragma unroll
        for (int off = 16; off > 0; off >>= 1) {
            s  += __shfl_xor_sync(0xffffffffu, s, off);
            sq += __shfl_xor_sync(0xffffffffu, sq, off);
        }
        if (lane == 0) {
            float mean = s * (1.f / 256.f);
            mean_sh[w] = mean;
            rstd_sh[w] = rsqrtf(sq * (1.f / 256.f) - mean * mean + LN_EPS);
        }
    }
    __syncthreads();
    #pragma unroll
    for (int rr = 0; rr < 4; rr++) {
        int r = rp * 4 + rr;
        out_node[(size_t)(bi0 + r) * INc + c] =
            (vsh[r][c] - mean_sh[r]) * rstd_sh[r] * gamma_x[c] + beta_x[c];
    }
    float z1a[4] = {0.f, 0.f, 0.f, 0.f}, z2a[4] = {0.f, 0.f, 0.f, 0.f};
    #pragma unroll 2
    for (int k = 0; k < INc; k++) {
        float w1 = Wedge[(size_t)k * INc + c];
        float w2 = Wedge[(size_t)(k + 256) * INc + c];
        #pragma unroll
        for (int rr = 0; rr < 4; rr++) {
            float npv = np_sh[rp * 4 + rr][k];
            z1a[rr] = fmaf(npv, w1, z1a[rr]);
            z2a[rr] = fmaf(npv, w2, z2a[rr]);
        }
    }
    #pragma unroll
    for (int rr = 0; rr < 4; rr++) {
        int r = rp * 4 + rr;
        g_z1[(size_t)(bi0 + r) * INc + c] = z1a[rr];
        g_z2[(size_t)(bi0 + r) * INc + c] = z2a[rr];
    }
}

// ============================================================
// K4: fp16 z3 GEMM + residual + LN. 256 thr, 8 warps, OCC 2.
// Block tile 64x256, K=256 in 8 k32 chunks, 3 stages (pitch-40
// halves, k2's validated layout). 8 wait+sync pairs (was 16).
// smem bytes: A16 0..33792 | B 3x20480 @33792..95232 |
//  Z1@95232 BE@96256 GA@97280 BT@98304 | Red@99328 RedQ@101376 |
//  Mean@103424 Rstd@103680 -> 103936  (x2 = 207.9KB, occ 2)
// ============================================================
#define K4_SMEM 103936
__global__ void __launch_bounds__(256, 2)
k4_fused(const float* __restrict__ emb_edge,
         const float* __restrict__ mask,
         const float* __restrict__ bedge,
         const float* __restrict__ gamma_e,
         const float* __restrict__ beta_e,
         float* __restrict__ out_edge) {
    extern __shared__ char sm[];
    uint32_t base = (uint32_t)__cvta_generic_to_shared(sm);
    uint32_t* sA   = (uint32_t*)sm;
    float*    sZ1  = (float*)(sm + 95232);
    float*    sBE  = (float*)(sm + 96256);
    float*    sGA  = (float*)(sm + 97280);
    float*    sBT  = (float*)(sm + 98304);
    float*    sRed = (float*)(sm + 99328);
    float*    sRedQ= (float*)(sm + 101376);
    float*    sMean= (float*)(sm + 103424);
    float*    sRstd= (float*)(sm + 103680);

    int t = threadIdx.x, wc = t >> 5, lane = t & 31;
    int g = lane >> 2, tig = lane & 3;
    int lm = lane & 7, lq = lane >> 3;
    int bid = blockIdx.x;
    int jt = bid & 3, i = (bid >> 2) & 255, b = bid >> 10;
    int j0 = jt * 64, bi = b * Nc + i, bN = b * Nc;
    float mi = mask[bi];

    // prefetch B chunks 0,1 (each 16KB data: 1024 cp16, 4/thread)
    #pragma unroll
    for (int s = 0; s < 2; s++) {
        #pragma unroll
        for (int q = 0; q < 4; q++) {
            int t8 = q * 256 + t;
            int n = t8 >> 2, kq = t8 & 3;
            cp16(base + 33792 + s * 20480 + (n * 20 + kq * 4) * 4,
                 g_W3H + (size_t)s * 8192 + (size_t)t8 * 8);
        }
        CP_COMMIT;
    }
    // stage A (masked xe -> fp16)
    #pragma unroll
    for (int u = 0; u < 16; u++) {
        int lin = u * 256 + t;
        int r = lin >> 6, c4 = lin & 63;
        float4 v = *(const float4*)(emb_edge +
            (((size_t)bi * Nc) + j0 + r) * INc + c4 * 4);
        float mm = mi * mask[bN + j0 + r];
        __half2 h01 = __floats2half2_rn(v.x * mm, v.y * mm);
        __half2 h23 = __floats2half2_rn(v.z * mm, v.w * mm);
        uint32_t* dst = sA + r * 132 + c4 * 2;
        dst[0] = *reinterpret_cast<uint32_t*>(&h01);
        dst[1] = *reinterpret_cast<uint32_t*>(&h23);
    }
    sZ1[t] = g_z1[(size_t)bi * INc + t];
    sBE[t] = bedge[t]; sGA[t] = gamma_e[t]; sBT[t] = beta_e[t];

    int aRow = lm + (lq & 1) * 8;
    int aColH = (lq >> 1) * 8;
    int bRowBase = wc * 32 + (lq >> 1) * 8 + lm;
    int bColH = (lq & 1) * 8;

    float acc[4][4][4];
    #pragma unroll
    for (int m = 0; m < 4; m++)
        #pragma unroll
        for (int n = 0; n < 4; n++)
            #pragma unroll
            for (int e = 0; e < 4; e++) acc[m][n][e] = 0.f;

    for (int c = 0; c < 8; c++) {
        if (c < 7) { CP_WAIT1; } else { CP_WAIT0; }
        __syncthreads();
        if (c + 2 < 8) {
            int cc = c + 2;
            #pragma unroll
            for (int q = 0; q < 4; q++) {
                int t8 = q * 256 + t;
                int n = t8 >> 2, kq = t8 & 3;
                cp16(base + 33792 + (cc % 3) * 20480 + (n * 20 + kq * 4) * 4,
                     g_W3H + (size_t)cc * 8192 + (size_t)t8 * 8);
            }
            CP_COMMIT;
        }
        uint32_t bO = base + 33792 + (c % 3) * 20480;
        #pragma unroll
        for (int kk = 0; kk < 2; kk++) {
            int kh = c * 32 + kk * 16;
            uint32_t af[4][4];
            uint32_t bf[2][4];
            #pragma unroll
            for (int mf = 0; mf < 4; mf++)
                ldsm4(af[mf], base + ((mf * 16 + aRow) * 264 + kh + aColH) * 2);
            #pragma unroll
            for (int p = 0; p < 2; p++)
                ldsm4(bf[p], bO + (uint32_t)((bRowBase + p * 16) * 40 + kk * 16 + bColH) * 2);
            #pragma unroll
            for (int p = 0; p < 2; p++)
                #pragma unroll
                for (int mf = 0; mf < 4; mf++) {
                    mma16(acc[mf][2 * p],     af[mf], bf[p][0], bf[p][1]);
                    mma16(acc[mf][2 * p + 1], af[mf], bf[p][2], bf[p][3]);
                }
        }
    }

    // ---- epilogue: residual + LayerNorm ----
    float vv[4][2][8];
    #pragma unroll
    for (int mf = 0; mf < 4; mf++) {
        #pragma unroll
        for (int rh = 0; rh < 2; rh++) {
            int r = mf * 16 + g + 8 * rh;
            int j = j0 + r;
            float mm = mi * mask[bN + j];
            const float* xerow = emb_edge + ((size_t)bi * Nc + j) * INc;
            const float* z2row = g_z2 + (size_t)(bN + j) * INc;
            float sum = 0.f, sq = 0.f;
            #pragma unroll
            for (int n = 0; n < 4; n++) {
                int c0 = wc * 32 + n * 8 + 2 * tig;
                float2 xe2 = *(const float2*)(xerow + c0);
                float2 z22 = *(const float2*)(z2row + c0);
                float2 z12 = *(const float2*)(sZ1 + c0);
                float2 be2 = *(const float2*)(sBE + c0);
                float v0 = acc[mf][n][2 * rh]     + xe2.x * mm + z12.x + z22.x + be2.x;
                float v1 = acc[mf][n][2 * rh + 1] + xe2.y * mm + z12.y + z22.y + be2.y;
                vv[mf][rh][2 * n] = v0; vv[mf][rh][2 * n + 1] = v1;
                sum += v0 + v1;
                sq = fmaf(v0, v0, sq); sq = fmaf(v1, v1, sq);
            }
            sum += __shfl_xor_sync(0xffffffffu, sum, 1);
            sum += __shfl_xor_sync(0xffffffffu, sum, 2);
            sq  += __shfl_xor_sync(0xffffffffu, sq, 1);
            sq  += __shfl_xor_sync(0xffffffffu, sq, 2);
            if (tig == 0) { sRed[r * 8 + wc] = sum; sRedQ[r * 8 + wc] = sq; }
        }
    }
    __syncthreads();
    if (t < 64) {
        float s = 0.f, ss = 0.f;
        #pragma unroll
        for (int k = 0; k < 8; k++) { s += sRed[t * 8 + k]; ss += sRedQ[t * 8 + k]; }
        float mean = s * (1.f / 256.f);
        float var = ss * (1.f / 256.f) - mean * mean;
        sMean[t] = mean; sRstd[t] = rsqrtf(var + LN_EPS);
    }
    __syncthreads();
    #pragma unroll
    for (int mf = 0; mf < 4; mf++) {
        #pragma unroll
        for (int rh = 0; rh < 2; rh++) {
            int r = mf * 16 + g + 8 * rh;
            int j = j0 + r;
            float mean = sMean[r], rs = sRstd[r];
            float* orow = out_edge + ((size_t)bi * Nc + j) * INc;
            #pragma unroll
            for (int n = 0; n < 4; n++) {
                int c0 = wc * 32 + n * 8 + 2 * tig;
                float2 ga2 = *(const float2*)(sGA + c0);
                float2 bt2 = *(const float2*)(sBT + c0);
                float2 o;
                o.x = (vv[mf][rh][2 * n]     - mean) * rs * ga2.x + bt2.x;
                o.y = (vv[mf][rh][2 * n + 1] - mean) * rs * ga2.y + bt2.y;
                *(float2*)(orow + c0) = o;
            }
        }
    }
}

// ============================================================
extern "C" void kernel_launch(void* const* d_in, const int* in_sizes, int n_in,
                              void* d_out, int out_size) {
    const float* emb_node = (const float*)d_in[0];
    const float* emb_edge = (const float*)d_in[1];
    const float* adj      = (const float*)d_in[2];
    const float* mask     = (const float*)d_in[3];
    const float* Ws       = (const float*)d_in[4];
    const float* Wt       = (const float*)d_in[5];
    const float* We       = (const float*)d_in[6];
    const float* attn     = (const float*)d_in[7];
    const float* Wn       = (const float*)d_in[8];
    const float* bn       = (const float*)d_in[9];
    const float* Wedge    = (const float*)d_in[10];
    const float* bedge    = (const float*)d_in[11];
    const float* gamma_x  = (const float*)d_in[12];
    const float* beta_x   = (const float*)d_in[13];
    const float* gamma_e  = (const float*)d_in[14];
    const float* beta_e   = (const float*)d_in[15];

    float* out_node = (float*)d_out;
    float* out_edge = out_node + Bc * Nc * INc;

    int dev = 0, nsm = 148;
    cudaGetDevice(&dev);
    cudaDeviceGetAttribute(&nsm, cudaDevAttrMultiProcessorCount, dev);

    cudaFuncSetAttribute(k2_scores, cudaFuncAttributeMaxDynamicSharedMemorySize,
                         K2_SMEM_B);
    cudaFuncSetAttribute(k3b_newnode, cudaFuncAttributeMaxDynamicSharedMemorySize,
                         K3B_SMEM_B);
    cudaFuncSetAttribute(k4_fused, cudaFuncAttributeMaxDynamicSharedMemorySize,
                         K4_SMEM);

    k0a_prep<<<256, 512>>>(We);
    k0b_prep<<<128, 512>>>(Wedge);
    k1_nodes<<<dim3(32, 2), 512>>>(emb_node, mask, Ws, Wt);
    k2_scores<<<nsm, 256, K2_SMEM_B>>>(emb_edge, adj, mask, attn);
    k3b_newnode<<<dim3(32, 2, 2), 512, K3B_SMEM_B>>>();
    k3c_node<<<64, 512>>>(Wn, bn, Wedge, gamma_x, beta_x, out_node);
    k4_fused<<<Bc * Nc * 4, 256, K4_SMEM>>>(emb_edge, mask, bedge,
                                            gamma_e, beta_e, out_edge);
}